// round 2
// baseline (speedup 1.0000x reference)
#include <cuda_runtime.h>
#include <math.h>

#define Bq   2
#define Nn   512
#define DIN  32
#define DHD  64
#define Hh   4
#define Cc   256
#define BN   (Bq*Nn)

typedef unsigned long long u64;

__device__ float g_ne[Nn*DHD];
__device__ float g_mbias[Nn*Nn];
__device__ float g_xl[BN*Cc];
__device__ float g_xr[BN*Cc];
__device__ float g_al[Hh*BN];
__device__ float g_ar[Hh*BN];
__device__ float g_attout[BN*Cc];
__device__ float g_hln[BN*Cc];

// ---- packed fp32x2 helpers (sm_100+/sm_103a) ----
__device__ __forceinline__ u64 add2(u64 a, u64 b) {
    u64 r; asm("add.rn.f32x2 %0,%1,%2;" : "=l"(r) : "l"(a), "l"(b)); return r;
}
__device__ __forceinline__ void fma2(u64 &d, u64 a, u64 b) {
    asm("fma.rn.f32x2 %0,%1,%2,%3;" : "=l"(d) : "l"(a), "l"(b), "l"(d));
}
__device__ __forceinline__ u64 mul2(u64 a, u64 b) {
    u64 r; asm("mul.rn.f32x2 %0,%1,%2;" : "=l"(r) : "l"(a), "l"(b)); return r;
}
__device__ __forceinline__ u64 dup2(float x) {
    u64 r; asm("mov.b64 %0,{%1,%1};" : "=l"(r) : "f"(x)); return r;
}
__device__ __forceinline__ float2 unpack2(u64 v) {
    float2 f; asm("mov.b64 {%0,%1},%2;" : "=f"(f.x), "=f"(f.y) : "l"(v)); return f;
}
#define ABS2MASK 0x7FFFFFFF7FFFFFFFULL

// ---------------- normalized embedding ----------------
__global__ void ne_kernel(const float* __restrict__ emb) {
    int i = blockIdx.x, t = threadIdx.x;
    float v = emb[i*DHD + t];
    float s = v*v;
    #pragma unroll
    for (int o = 16; o; o >>= 1) s += __shfl_xor_sync(0xffffffffu, s, o);
    __shared__ float sm[2];
    if ((t & 31) == 0) sm[t >> 5] = s;
    __syncthreads();
    float inv = rsqrtf(sm[0] + sm[1]);
    g_ne[i*DHD + t] = v * inv;
}

// ---------------- mask bias: (ne @ ne^T != 0) | eye -> 0 / -1e30 ----------
// 32x64 tiles, grid (8,16) = 128 blocks
__global__ void __launch_bounds__(256) mask_kernel() {
    __shared__ float A_s[32][65];
    __shared__ float B_s[64][65];
    int i0 = blockIdx.y * 32, j0 = blockIdx.x * 64;
    int t = threadIdx.x, tx = t & 15, ty = t >> 4;

    #pragma unroll
    for (int p = 0; p < 8; p++) {
        int idx = t + p*256;
        int r = idx >> 6, d = idx & 63;
        A_s[r][d] = g_ne[(i0 + r)*DHD + d];
    }
    #pragma unroll
    for (int p = 0; p < 16; p++) {
        int idx = t + p*256;
        int r = idx >> 6, d = idx & 63;
        B_s[r][d] = g_ne[(j0 + r)*DHD + d];
    }
    __syncthreads();

    float acc[2][4];
    #pragma unroll
    for (int r = 0; r < 2; r++)
        #pragma unroll
        for (int c = 0; c < 4; c++) acc[r][c] = 0.f;

    #pragma unroll
    for (int kk = 0; kk < 64; kk++) {
        float a0 = A_s[ty][kk], a1 = A_s[ty + 16][kk];
        float bb[4];
        #pragma unroll
        for (int c = 0; c < 4; c++) bb[c] = B_s[4*tx + c][kk];
        #pragma unroll
        for (int c = 0; c < 4; c++) { acc[0][c] += a0*bb[c]; acc[1][c] += a1*bb[c]; }
    }
    #pragma unroll
    for (int r = 0; r < 2; r++) {
        int gi = i0 + ty + 16*r;
        float4 o;
        float* op = &o.x;
        #pragma unroll
        for (int c = 0; c < 4; c++) {
            int gj = j0 + 4*tx + c;
            op[c] = (acc[r][c] != 0.0f || gi == gj) ? 0.0f : -1e30f;
        }
        *reinterpret_cast<float4*>(&g_mbias[gi*Nn + j0 + 4*tx]) = o;
    }
}

// ---------------- projection: xl AND xr in one launch (z = l/r) -----------
template<int K>
__global__ void __launch_bounds__(256) proj_kernel(
    const float* __restrict__ Xopt,
    const float* __restrict__ Wl, const float* __restrict__ bl,
    const float* __restrict__ Wr, const float* __restrict__ br)
{
    const float* X    = Xopt ? Xopt : g_hln;
    const float* W    = blockIdx.z ? Wr : Wl;
    const float* bias = blockIdx.z ? br : bl;
    float* outp       = blockIdx.z ? g_xr : g_xl;

    __shared__ float A_s[64][33];
    __shared__ float W_s[32][68];
    int m0 = blockIdx.y * 64, n0 = blockIdx.x * 64;
    int t = threadIdx.x, tx = t & 15, ty = t >> 4;

    u64 accp[4][2];
    #pragma unroll
    for (int r = 0; r < 4; r++) { accp[r][0] = 0ull; accp[r][1] = 0ull; }

    for (int kc = 0; kc < K; kc += 32) {
        __syncthreads();
        #pragma unroll
        for (int p = 0; p < 8; p++) {
            int row = (t >> 5) + p*8;
            int col = t & 31;
            A_s[row][col] = X[(m0 + row)*K + kc + col];
        }
        #pragma unroll
        for (int p = 0; p < 8; p++) {
            int kk  = (t >> 6) + p*4;
            int col = t & 63;
            W_s[kk][col] = W[(kc + kk)*Cc + n0 + col];
        }
        __syncthreads();
        #pragma unroll
        for (int kk = 0; kk < 32; kk++) {
            ulonglong2 bv = *reinterpret_cast<const ulonglong2*>(&W_s[kk][4*tx]);
            #pragma unroll
            for (int r = 0; r < 4; r++) {
                u64 ad = dup2(A_s[ty + 16*r][kk]);
                fma2(accp[r][0], ad, bv.x);
                fma2(accp[r][1], ad, bv.y);
            }
        }
    }
    float4 bv4 = *reinterpret_cast<const float4*>(&bias[n0 + 4*tx]);
    #pragma unroll
    for (int r = 0; r < 4; r++) {
        float2 lo = unpack2(accp[r][0]), hi = unpack2(accp[r][1]);
        float4 o = make_float4(lo.x + bv4.x, lo.y + bv4.y, hi.x + bv4.z, hi.y + bv4.w);
        *reinterpret_cast<float4*>(&outp[(m0 + ty + 16*r)*Cc + n0 + 4*tx]) = o;
    }
}

// ---------------- rank-1 score terms: 0.6 * att_h . (xl|xr) ----------------
__global__ void av_kernel(const float* __restrict__ att) {
    int m = blockIdx.x;
    int t = threadIdx.x, w = t >> 5, l = t & 31, hh = w & 3;
    const float* src = (w < 4) ? g_xl : g_xr;
    float v = src[m*Cc + hh*64 + l]      * att[hh*64 + l]
            + src[m*Cc + hh*64 + 32 + l] * att[hh*64 + 32 + l];
    #pragma unroll
    for (int o = 16; o; o >>= 1) v += __shfl_xor_sync(0xffffffffu, v, o);
    if (l == 0) {
        float* dst = (w < 4) ? g_al : g_ar;
        dst[hh*BN + m] = 0.6f * v;
    }
}

// ---------------- fused GATv2 attention, packed f32x2, 16 rows/block -------
// grid (32, 4, 2) = 256 blocks, 256 threads. Warp w owns rows 2w, 2w+1.
// Lane l owns j columns 2l, 2l+1 (scores) and d columns 2l, 2l+1 (output).
__global__ void __launch_bounds__(256) attn_kernel(
    const float* __restrict__ att,
    const float* __restrict__ bias,
    float* __restrict__ outopt)
{
    float* out = outopt ? outopt : g_attout;
    const int b = blockIdx.z, h = blockIdx.y, i0 = blockIdx.x * 16;
    const int t = threadIdx.x, w = t >> 5, l = t & 31;

    __shared__ float  xr_s[16][64];
    __shared__ float  xl_s[64][68];
    __shared__ float2 p2_s[16][64];
    __shared__ float  batt_s[64];
    __shared__ float  al_s[64];

    {   // load xr (16x64): one float4 per thread
        int r = t >> 4, cc = t & 15;
        float4 v = *reinterpret_cast<const float4*>(&g_xr[(b*Nn + i0 + r)*Cc + h*64 + 4*cc]);
        *reinterpret_cast<float4*>(&xr_s[r][4*cc]) = v;
    }
    if (t < 64) batt_s[t] = 0.4f * att[h*64 + t];
    __syncthreads();

    float arr[2];
    #pragma unroll
    for (int k = 0; k < 2; k++) arr[k] = g_ar[h*BN + b*Nn + i0 + 2*w + k];

    float m_run[2], l_run[2];
    u64 accp[2];
    #pragma unroll
    for (int k = 0; k < 2; k++) { m_run[k] = -3.0e38f; l_run[k] = 0.f; accp[k] = 0ull; }

    for (int c = 0; c < 8; c++) {
        const int j0 = c * 64;
        __syncthreads();   // previous chunk's aggregation done with xl_s
        #pragma unroll
        for (int p = 0; p < 4; p++) {
            int idx = t + p*256;              // float4 units: 0..1023
            int jj = idx >> 4, cc = idx & 15;
            float4 v = *reinterpret_cast<const float4*>(&g_xl[(b*Nn + j0 + jj)*Cc + h*64 + 4*cc]);
            *reinterpret_cast<float4*>(&xl_s[jj][4*cc]) = v;
        }
        if (t < 64) al_s[t] = g_al[h*BN + b*Nn + j0 + t];
        __syncthreads();

        // ---- score: s[k][j] = sum_d 0.4*att_d * |xr[k][d] + xl[j][d]| ----
        u64 s0p[2] = {0ull, 0ull}, s1p[2] = {0ull, 0ull};
        const ulonglong2* xl0 = reinterpret_cast<const ulonglong2*>(&xl_s[2*l][0]);
        const ulonglong2* xl1 = reinterpret_cast<const ulonglong2*>(&xl_s[2*l + 1][0]);
        const ulonglong2* bt  = reinterpret_cast<const ulonglong2*>(batt_s);
        #pragma unroll
        for (int q = 0; q < 16; q++) {
            ulonglong2 bv = bt[q];
            ulonglong2 a0 = xl0[q];
            ulonglong2 a1 = xl1[q];
            #pragma unroll
            for (int k = 0; k < 2; k++) {
                ulonglong2 rv = *reinterpret_cast<const ulonglong2*>(&xr_s[2*w + k][4*q]);
                u64 z;
                z = add2(rv.x, a0.x) & ABS2MASK; fma2(s0p[k], bv.x, z);
                z = add2(rv.y, a0.y) & ABS2MASK; fma2(s0p[k], bv.y, z);
                z = add2(rv.x, a1.x) & ABS2MASK; fma2(s1p[k], bv.x, z);
                z = add2(rv.y, a1.y) & ABS2MASK; fma2(s1p[k], bv.y, z);
            }
        }
        float alj0 = al_s[2*l], alj1 = al_s[2*l + 1];

        // ---- online softmax update ----
        #pragma unroll
        for (int k = 0; k < 2; k++) {
            float2 mb = *reinterpret_cast<const float2*>(&g_mbias[(i0 + 2*w + k)*Nn + j0 + 2*l]);
            float2 t0 = unpack2(s0p[k]);
            float2 t1 = unpack2(s1p[k]);
            float s0 = t0.x + t0.y + arr[k] + alj0 + mb.x;
            float s1 = t1.x + t1.y + arr[k] + alj1 + mb.y;

            float mloc = fmaxf(s0, s1);
            #pragma unroll
            for (int o = 16; o; o >>= 1) mloc = fmaxf(mloc, __shfl_xor_sync(0xffffffffu, mloc, o));
            float mnew = fmaxf(m_run[k], mloc);
            float corr = __expf(m_run[k] - mnew);
            m_run[k] = mnew;
            float p0 = __expf(s0 - mnew);
            float p1 = __expf(s1 - mnew);
            p2_s[2*w + k][2*l]     = make_float2(p0, p0);
            p2_s[2*w + k][2*l + 1] = make_float2(p1, p1);
            float ps = p0 + p1;
            #pragma unroll
            for (int o = 16; o; o >>= 1) ps += __shfl_xor_sync(0xffffffffu, ps, o);
            l_run[k] = l_run[k]*corr + ps;
            accp[k] = mul2(accp[k], dup2(corr));
        }
        __syncwarp();

        // ---- aggregation: acc[k][d-pair] += p[k][jj] * xl[jj][d-pair] ----
        #pragma unroll 8
        for (int jj = 0; jj < 64; jj++) {
            u64 xv = *reinterpret_cast<const u64*>(&xl_s[jj][2*l]);
            #pragma unroll
            for (int k = 0; k < 2; k++) {
                u64 pk = *reinterpret_cast<const u64*>(&p2_s[2*w + k][jj]);
                fma2(accp[k], pk, xv);
            }
        }
    }

    float2 bv = *reinterpret_cast<const float2*>(&bias[h*64 + 2*l]);
    #pragma unroll
    for (int k = 0; k < 2; k++) {
        float inv = 1.0f / l_run[k];
        float2 a = unpack2(accp[k]);
        int i = i0 + 2*w + k;
        float2 o = make_float2(a.x*inv + bv.x, a.y*inv + bv.y);
        *reinterpret_cast<float2*>(&out[(b*Nn + i)*Cc + h*64 + 2*l]) = o;
    }
}

// ---------------- LayerNorm (+ optional ReLU) ------------------------------
__device__ __forceinline__ float block_sum256(float v) {
    #pragma unroll
    for (int o = 16; o; o >>= 1) v += __shfl_xor_sync(0xffffffffu, v, o);
    __shared__ float red[8];
    int w = threadIdx.x >> 5;
    if ((threadIdx.x & 31) == 0) red[w] = v;
    __syncthreads();
    v = red[0]+red[1]+red[2]+red[3]+red[4]+red[5]+red[6]+red[7];
    __syncthreads();
    return v;
}

__global__ void ln_kernel(const float* __restrict__ g,
                          const float* __restrict__ be,
                          float* __restrict__ outopt,
                          int do_relu)
{
    float* out = outopt ? outopt : g_hln;
    int m = blockIdx.x, t = threadIdx.x;
    float v = g_attout[m*Cc + t];
    float mu = block_sum256(v) * (1.0f/Cc);
    float d = v - mu;
    float var = block_sum256(d*d) * (1.0f/Cc);
    float o = d * rsqrtf(var + 1e-5f) * g[t] + be[t];
    if (do_relu) o = fmaxf(o, 0.0f);
    out[m*Cc + t] = o;
}

// ---------------- launch ----------------------------------------------------
extern "C" void kernel_launch(void* const* d_in, const int* in_sizes, int n_in,
                              void* d_out, int out_size) {
    const float* x     = (const float*)d_in[0];
    const float* emb   = (const float*)d_in[1];
    const float* w1l   = (const float*)d_in[2];
    const float* b1l   = (const float*)d_in[3];
    const float* w1r   = (const float*)d_in[4];
    const float* b1r   = (const float*)d_in[5];
    const float* att1  = (const float*)d_in[6];
    const float* bias1 = (const float*)d_in[7];
    const float* g1    = (const float*)d_in[8];
    const float* be1   = (const float*)d_in[9];
    const float* w2l   = (const float*)d_in[10];
    const float* b2l   = (const float*)d_in[11];
    const float* w2r   = (const float*)d_in[12];
    const float* b2r   = (const float*)d_in[13];
    const float* att2  = (const float*)d_in[14];
    const float* bias2 = (const float*)d_in[15];
    const float* g2    = (const float*)d_in[16];
    const float* be2   = (const float*)d_in[17];
    float* out = (float*)d_out;

    ne_kernel<<<Nn, DHD>>>(emb);
    mask_kernel<<<dim3(8, 16), 256>>>();

    proj_kernel<DIN><<<dim3(4, 16, 2), 256>>>(x, w1l, b1l, w1r, b1r);
    av_kernel<<<BN, 256>>>(att1);
    attn_kernel<<<dim3(32, 4, 2), 256>>>(att1, bias1, nullptr);
    ln_kernel<<<BN, 256>>>(g1, be1, nullptr, 1);

    proj_kernel<Cc><<<dim3(4, 16, 2), 256>>>(nullptr, w2l, b2l, w2r, b2r);
    av_kernel<<<BN, 256>>>(att2);
    attn_kernel<<<dim3(32, 4, 2), 256>>>(att2, bias2, nullptr);
    ln_kernel<<<BN, 256>>>(g2, be2, out, 0);
}

// round 3
// speedup vs baseline: 1.0812x; 1.0812x over previous
#include <cuda_runtime.h>
#include <math.h>

#define Bq   2
#define Nn   512
#define DIN  32
#define DHD  64
#define Hh   4
#define Cc   256
#define BN   (Bq*Nn)

typedef unsigned long long u64;

__device__ float g_ne[Nn*DHD];
__device__ float g_mbias[Nn*Nn];
__device__ float g_xl[BN*Cc];
__device__ float g_xr[BN*Cc];
__device__ float g_attout[BN*Cc];
__device__ float g_hln[BN*Cc];

// ---- packed fp32x2 helpers (sm_103a) ----
__device__ __forceinline__ u64 add2(u64 a, u64 b) {
    u64 r; asm("add.rn.f32x2 %0,%1,%2;" : "=l"(r) : "l"(a), "l"(b)); return r;
}
__device__ __forceinline__ void fma2(u64 &d, u64 a, u64 b) {
    asm("fma.rn.f32x2 %0,%1,%2,%3;" : "=l"(d) : "l"(a), "l"(b), "l"(d));
}
__device__ __forceinline__ u64 dup2(float x) {
    u64 r; asm("mov.b64 %0,{%1,%1};" : "=l"(r) : "f"(x)); return r;
}
__device__ __forceinline__ float2 unpack2(u64 v) {
    float2 f; asm("mov.b64 {%0,%1},%2;" : "=f"(f.x), "=f"(f.y) : "l"(v)); return f;
}
#define ABS2MASK 0x7FFFFFFF7FFFFFFFULL

// ---------------- normalized embedding ----------------
__global__ void ne_kernel(const float* __restrict__ emb) {
    int i = blockIdx.x, t = threadIdx.x;
    float v = emb[i*DHD + t];
    float s = v*v;
    #pragma unroll
    for (int o = 16; o; o >>= 1) s += __shfl_xor_sync(0xffffffffu, s, o);
    __shared__ float sm[2];
    if ((t & 31) == 0) sm[t >> 5] = s;
    __syncthreads();
    float inv = rsqrtf(sm[0] + sm[1]);
    g_ne[i*DHD + t] = v * inv;
}

// ---------------- mask bias: (ne @ ne^T != 0) | eye -> 0 / -1e30 ----------
__global__ void __launch_bounds__(256) mask_kernel() {
    __shared__ float A_s[32][65];
    __shared__ float B_s[64][65];
    int i0 = blockIdx.y * 32, j0 = blockIdx.x * 64;
    int t = threadIdx.x, tx = t & 15, ty = t >> 4;

    #pragma unroll
    for (int p = 0; p < 8; p++) {
        int idx = t + p*256;
        int r = idx >> 6, d = idx & 63;
        A_s[r][d] = g_ne[(i0 + r)*DHD + d];
    }
    #pragma unroll
    for (int p = 0; p < 16; p++) {
        int idx = t + p*256;
        int r = idx >> 6, d = idx & 63;
        B_s[r][d] = g_ne[(j0 + r)*DHD + d];
    }
    __syncthreads();

    float acc[2][4];
    #pragma unroll
    for (int r = 0; r < 2; r++)
        #pragma unroll
        for (int c = 0; c < 4; c++) acc[r][c] = 0.f;

    #pragma unroll
    for (int kk = 0; kk < 64; kk++) {
        float a0 = A_s[ty][kk], a1 = A_s[ty + 16][kk];
        float bb[4];
        #pragma unroll
        for (int c = 0; c < 4; c++) bb[c] = B_s[4*tx + c][kk];
        #pragma unroll
        for (int c = 0; c < 4; c++) { acc[0][c] += a0*bb[c]; acc[1][c] += a1*bb[c]; }
    }
    #pragma unroll
    for (int r = 0; r < 2; r++) {
        int gi = i0 + ty + 16*r;
        float4 o;
        float* op = &o.x;
        #pragma unroll
        for (int c = 0; c < 4; c++) {
            int gj = j0 + 4*tx + c;
            op[c] = (acc[r][c] != 0.0f || gi == gj) ? 0.0f : -1e30f;
        }
        *reinterpret_cast<float4*>(&g_mbias[gi*Nn + j0 + 4*tx]) = o;
    }
}

// ---------------- projection: xl AND xr in one launch (z = l/r) -----------
template<int K>
__global__ void __launch_bounds__(256) proj_kernel(
    const float* __restrict__ Xopt,
    const float* __restrict__ Wl, const float* __restrict__ bl,
    const float* __restrict__ Wr, const float* __restrict__ br)
{
    const float* X    = Xopt ? Xopt : g_hln;
    const float* W    = blockIdx.z ? Wr : Wl;
    const float* bias = blockIdx.z ? br : bl;
    float* outp       = blockIdx.z ? g_xr : g_xl;

    __shared__ float A_s[64][33];
    __shared__ float W_s[32][68];
    int m0 = blockIdx.y * 64, n0 = blockIdx.x * 64;
    int t = threadIdx.x, tx = t & 15, ty = t >> 4;

    u64 accp[4][2];
    #pragma unroll
    for (int r = 0; r < 4; r++) { accp[r][0] = 0ull; accp[r][1] = 0ull; }

    for (int kc = 0; kc < K; kc += 32) {
        __syncthreads();
        #pragma unroll
        for (int p = 0; p < 8; p++) {
            int row = (t >> 5) + p*8;
            int col = t & 31;
            A_s[row][col] = X[(m0 + row)*K + kc + col];
        }
        #pragma unroll
        for (int p = 0; p < 8; p++) {
            int kk  = (t >> 6) + p*4;
            int col = t & 63;
            W_s[kk][col] = W[(kc + kk)*Cc + n0 + col];
        }
        __syncthreads();
        #pragma unroll
        for (int kk = 0; kk < 32; kk++) {
            ulonglong2 bv = *reinterpret_cast<const ulonglong2*>(&W_s[kk][4*tx]);
            #pragma unroll
            for (int r = 0; r < 4; r++) {
                u64 ad = dup2(A_s[ty + 16*r][kk]);
                fma2(accp[r][0], ad, bv.x);
                fma2(accp[r][1], ad, bv.y);
            }
        }
    }
    float4 bv4 = *reinterpret_cast<const float4*>(&bias[n0 + 4*tx]);
    #pragma unroll
    for (int r = 0; r < 4; r++) {
        float2 lo = unpack2(accp[r][0]), hi = unpack2(accp[r][1]);
        float4 o = make_float4(lo.x + bv4.x, lo.y + bv4.y, hi.x + bv4.z, hi.y + bv4.w);
        *reinterpret_cast<float4*>(&outp[(m0 + ty + 16*r)*Cc + n0 + 4*tx]) = o;
    }
}

// ---------------- fused GATv2 attention -----------------------------------
// grid (16, 4, 2), 256 threads. 32 rows/block; warp w owns rows 4w..4w+3.
// Lane l owns j columns 2l,2l+1 (scores) and d columns 2l,2l+1 (output).
// No online max: scores are O(1); masked = -1e30 -> exp = 0 exactly.
__global__ void __launch_bounds__(256) attn_kernel(
    const float* __restrict__ att,
    const float* __restrict__ bias,
    float* __restrict__ outopt)
{
    float* out = outopt ? outopt : g_attout;
    const int b = blockIdx.z, h = blockIdx.y, i0 = blockIdx.x * 32;
    const int t = threadIdx.x, w = t >> 5, l = t & 31;

    __shared__ float  xr2_s[32][128];   // duplicated pairs: [row][2d]=(v,v)
    __shared__ float  xl_s[64][68];     // row-major (aggregation)
    __shared__ float  xlT[64][66];      // transposed [d][j] (score)
    __shared__ float2 p2_s[32][64];     // duplicated probabilities
    __shared__ float2 batt2[64];        // (0.4*att, 0.4*att)
    __shared__ float2 catt2[64];        // (0.6*att, 0.6*att)

    // load xr duplicated-pairs: 512 float4 reads -> 2 per thread
    #pragma unroll
    for (int p = 0; p < 2; p++) {
        int idx = t + p*256;            // float4 index over 32x16
        int r = idx >> 4, cc = idx & 15;
        float4 v = *reinterpret_cast<const float4*>(&g_xr[(b*Nn + i0 + r)*Cc + h*64 + 4*cc]);
        *reinterpret_cast<float4*>(&xr2_s[r][8*cc])     = make_float4(v.x, v.x, v.y, v.y);
        *reinterpret_cast<float4*>(&xr2_s[r][8*cc + 4]) = make_float4(v.z, v.z, v.w, v.w);
    }
    if (t < 64) {
        float a = att[h*64 + t];
        batt2[t] = make_float2(0.4f*a, 0.4f*a);
        catt2[t] = make_float2(0.6f*a, 0.6f*a);
    }
    __syncthreads();

    // ar[k] = 0.6 * sum_d att_d * xr[row][d], once per warp (all lanes get it)
    float arr[4];
    #pragma unroll
    for (int k = 0; k < 4; k++) {
        int row = 4*w + k;
        float pa = catt2[l].x      * xr2_s[row][2*l]
                 + catt2[l + 32].x * xr2_s[row][2*(l + 32)];
        #pragma unroll
        for (int o = 16; o; o >>= 1) pa += __shfl_xor_sync(0xffffffffu, pa, o);
        arr[k] = pa;
    }

    u64 accp[4];
    float psum[4];
    #pragma unroll
    for (int k = 0; k < 4; k++) { accp[k] = 0ull; psum[k] = 0.f; }

    for (int c = 0; c < 8; c++) {
        const int j0 = c * 64;
        __syncthreads();   // previous chunk done with xl_s / p2_s
        #pragma unroll
        for (int p = 0; p < 4; p++) {
            int idx = t + p*256;            // float4 units over 64x16
            int jj = idx >> 4, cc = idx & 15;
            float4 v = *reinterpret_cast<const float4*>(&g_xl[(b*Nn + j0 + jj)*Cc + h*64 + 4*cc]);
            *reinterpret_cast<float4*>(&xl_s[jj][4*cc]) = v;
            xlT[4*cc    ][jj] = v.x;
            xlT[4*cc + 1][jj] = v.y;
            xlT[4*cc + 2][jj] = v.z;
            xlT[4*cc + 3][jj] = v.w;
        }
        __syncthreads();

        // ---- score + al, over d (conflict-free LDS) ----
        u64 sp[4] = {0ull, 0ull, 0ull, 0ull};
        u64 alp = 0ull;
        #pragma unroll 16
        for (int d = 0; d < 64; d++) {
            u64 xl2 = *reinterpret_cast<const u64*>(&xlT[d][2*l]);
            u64 bt  = *reinterpret_cast<const u64*>(&batt2[d]);
            u64 ct  = *reinterpret_cast<const u64*>(&catt2[d]);
            fma2(alp, ct, xl2);
            #pragma unroll
            for (int k = 0; k < 4; k++) {
                u64 xr2 = *reinterpret_cast<const u64*>(&xr2_s[4*w + k][2*d]);
                u64 z = add2(xr2, xl2) & ABS2MASK;
                fma2(sp[k], bt, z);
            }
        }
        float2 al2 = unpack2(alp);

        // ---- exp + probability write (no max shift needed) ----
        #pragma unroll
        for (int k = 0; k < 4; k++) {
            float2 mb = *reinterpret_cast<const float2*>(&g_mbias[(i0 + 4*w + k)*Nn + j0 + 2*l]);
            float2 sv = unpack2(sp[k]);
            float p0 = __expf(sv.x + arr[k] + al2.x + mb.x);
            float p1 = __expf(sv.y + arr[k] + al2.y + mb.y);
            *reinterpret_cast<float4*>(&p2_s[4*w + k][2*l]) = make_float4(p0, p0, p1, p1);
            psum[k] += p0 + p1;
        }
        __syncwarp();

        // ---- aggregation: acc[k][d-pair] += p[k][jj] * xl[jj][d-pair] ----
        #pragma unroll 8
        for (int jj = 0; jj < 64; jj++) {
            u64 xv = *reinterpret_cast<const u64*>(&xl_s[jj][2*l]);
            #pragma unroll
            for (int k = 0; k < 4; k++) {
                u64 pk = *reinterpret_cast<const u64*>(&p2_s[4*w + k][jj]);
                fma2(accp[k], pk, xv);
            }
        }
    }

    float2 bv = *reinterpret_cast<const float2*>(&bias[h*64 + 2*l]);
    #pragma unroll
    for (int k = 0; k < 4; k++) {
        float s = psum[k];
        #pragma unroll
        for (int o = 16; o; o >>= 1) s += __shfl_xor_sync(0xffffffffu, s, o);
        float inv = 1.0f / s;
        float2 a = unpack2(accp[k]);
        int i = i0 + 4*w + k;
        float2 o2 = make_float2(a.x*inv + bv.x, a.y*inv + bv.y);
        *reinterpret_cast<float2*>(&out[(b*Nn + i)*Cc + h*64 + 2*l]) = o2;
    }
}

// ---------------- LayerNorm (+ optional ReLU) ------------------------------
__device__ __forceinline__ float block_sum256(float v) {
    #pragma unroll
    for (int o = 16; o; o >>= 1) v += __shfl_xor_sync(0xffffffffu, v, o);
    __shared__ float red[8];
    int w = threadIdx.x >> 5;
    if ((threadIdx.x & 31) == 0) red[w] = v;
    __syncthreads();
    v = red[0]+red[1]+red[2]+red[3]+red[4]+red[5]+red[6]+red[7];
    __syncthreads();
    return v;
}

__global__ void ln_kernel(const float* __restrict__ g,
                          const float* __restrict__ be,
                          float* __restrict__ outopt,
                          int do_relu)
{
    float* out = outopt ? outopt : g_hln;
    int m = blockIdx.x, t = threadIdx.x;
    float v = g_attout[m*Cc + t];
    float mu = block_sum256(v) * (1.0f/Cc);
    float d = v - mu;
    float var = block_sum256(d*d) * (1.0f/Cc);
    float o = d * rsqrtf(var + 1e-5f) * g[t] + be[t];
    if (do_relu) o = fmaxf(o, 0.0f);
    out[m*Cc + t] = o;
}

// ---------------- launch ----------------------------------------------------
extern "C" void kernel_launch(void* const* d_in, const int* in_sizes, int n_in,
                              void* d_out, int out_size) {
    const float* x     = (const float*)d_in[0];
    const float* emb   = (const float*)d_in[1];
    const float* w1l   = (const float*)d_in[2];
    const float* b1l   = (const float*)d_in[3];
    const float* w1r   = (const float*)d_in[4];
    const float* b1r   = (const float*)d_in[5];
    const float* att1  = (const float*)d_in[6];
    const float* bias1 = (const float*)d_in[7];
    const float* g1    = (const float*)d_in[8];
    const float* be1   = (const float*)d_in[9];
    const float* w2l   = (const float*)d_in[10];
    const float* b2l   = (const float*)d_in[11];
    const float* w2r   = (const float*)d_in[12];
    const float* b2r   = (const float*)d_in[13];
    const float* att2  = (const float*)d_in[14];
    const float* bias2 = (const float*)d_in[15];
    const float* g2    = (const float*)d_in[16];
    const float* be2   = (const float*)d_in[17];
    float* out = (float*)d_out;

    ne_kernel<<<Nn, DHD>>>(emb);
    mask_kernel<<<dim3(8, 16), 256>>>();

    proj_kernel<DIN><<<dim3(4, 16, 2), 256>>>(x, w1l, b1l, w1r, b1r);
    attn_kernel<<<dim3(16, 4, 2), 256>>>(att1, bias1, nullptr);
    ln_kernel<<<BN, 256>>>(g1, be1, nullptr, 1);

    proj_kernel<Cc><<<dim3(4, 16, 2), 256>>>(nullptr, w2l, b2l, w2r, b2r);
    attn_kernel<<<dim3(16, 4, 2), 256>>>(att2, bias2, nullptr);
    ln_kernel<<<BN, 256>>>(g2, be2, out, 0);
}

// round 4
// speedup vs baseline: 1.2860x; 1.1895x over previous
#include <cuda_runtime.h>
#include <math.h>

#define Bq   2
#define Nn   512
#define DIN  32
#define DHD  64
#define Hh   4
#define Cc   256
#define BN   (Bq*Nn)

typedef unsigned long long u64;

__device__ float  g_mbias[Nn*Nn];
__device__ float2 g_xlT[Bq*Hh*32*512];   // [(b*4+h)*32 + d2][node] : (xl[j][2d2], xl[j][2d2+1])
__device__ float  g_xr[BN*Cc];
__device__ float  g_attout[BN*Cc];
__device__ float  g_hln[BN*Cc];

// ---- packed fp32x2 helpers (sm_103a) ----
__device__ __forceinline__ u64 add2(u64 a, u64 b) {
    u64 r; asm("add.rn.f32x2 %0,%1,%2;" : "=l"(r) : "l"(a), "l"(b)); return r;
}
__device__ __forceinline__ void fma2(u64 &d, u64 a, u64 b) {
    asm("fma.rn.f32x2 %0,%1,%2,%3;" : "=l"(d) : "l"(a), "l"(b), "l"(d));
}
__device__ __forceinline__ u64 dup2(float x) {
    u64 r; asm("mov.b64 %0,{%1,%1};" : "=l"(r) : "f"(x)); return r;
}
__device__ __forceinline__ float2 unpack2(u64 v) {
    float2 f; asm("mov.b64 {%0,%1},%2;" : "=f"(f.x), "=f"(f.y) : "l"(v)); return f;
}
#define ABS2MASK 0x7FFFFFFF7FFFFFFFULL

// ---------------- mask bias (ne fused): (ne@ne^T != 0)|eye -> 0/-1e30 ------
__global__ void __launch_bounds__(256) mask_kernel(const float* __restrict__ emb) {
    __shared__ float A_s[32][65];
    __shared__ float B_s[64][65];
    int i0 = blockIdx.y * 32, j0 = blockIdx.x * 64;
    int t = threadIdx.x, tx = t & 15, ty = t >> 4;

    {   // normalize A rows: 8 threads per row, 8 vals each
        int r = t >> 3, q = t & 7;
        const float* src = &emb[(i0 + r)*DHD + q*8];
        float4 v0 = *reinterpret_cast<const float4*>(src);
        float4 v1 = *reinterpret_cast<const float4*>(src + 4);
        float s = v0.x*v0.x + v0.y*v0.y + v0.z*v0.z + v0.w*v0.w
                + v1.x*v1.x + v1.y*v1.y + v1.z*v1.z + v1.w*v1.w;
        s += __shfl_xor_sync(0xffffffffu, s, 1);
        s += __shfl_xor_sync(0xffffffffu, s, 2);
        s += __shfl_xor_sync(0xffffffffu, s, 4);
        float inv = rsqrtf(s);
        A_s[r][q*8+0]=v0.x*inv; A_s[r][q*8+1]=v0.y*inv; A_s[r][q*8+2]=v0.z*inv; A_s[r][q*8+3]=v0.w*inv;
        A_s[r][q*8+4]=v1.x*inv; A_s[r][q*8+5]=v1.y*inv; A_s[r][q*8+6]=v1.z*inv; A_s[r][q*8+7]=v1.w*inv;
    }
    {   // normalize B rows: 4 threads per row, 16 vals each
        int r = t >> 2, q = t & 3;
        const float* src = &emb[(j0 + r)*DHD + q*16];
        float4 v[4];
        #pragma unroll
        for (int i = 0; i < 4; i++) v[i] = *reinterpret_cast<const float4*>(src + 4*i);
        float s = 0.f;
        #pragma unroll
        for (int i = 0; i < 4; i++) s += v[i].x*v[i].x + v[i].y*v[i].y + v[i].z*v[i].z + v[i].w*v[i].w;
        s += __shfl_xor_sync(0xffffffffu, s, 1);
        s += __shfl_xor_sync(0xffffffffu, s, 2);
        float inv = rsqrtf(s);
        #pragma unroll
        for (int i = 0; i < 4; i++) {
            B_s[r][q*16 + 4*i    ] = v[i].x*inv;
            B_s[r][q*16 + 4*i + 1] = v[i].y*inv;
            B_s[r][q*16 + 4*i + 2] = v[i].z*inv;
            B_s[r][q*16 + 4*i + 3] = v[i].w*inv;
        }
    }
    __syncthreads();

    float acc[2][4];
    #pragma unroll
    for (int r = 0; r < 2; r++)
        #pragma unroll
        for (int c = 0; c < 4; c++) acc[r][c] = 0.f;

    #pragma unroll
    for (int kk = 0; kk < 64; kk++) {
        float a0 = A_s[ty][kk], a1 = A_s[ty + 16][kk];
        float bb[4];
        #pragma unroll
        for (int c = 0; c < 4; c++) bb[c] = B_s[4*tx + c][kk];
        #pragma unroll
        for (int c = 0; c < 4; c++) { acc[0][c] += a0*bb[c]; acc[1][c] += a1*bb[c]; }
    }
    #pragma unroll
    for (int r = 0; r < 2; r++) {
        int gi = i0 + ty + 16*r;
        float4 o;
        float* op = &o.x;
        #pragma unroll
        for (int c = 0; c < 4; c++) {
            int gj = j0 + 4*tx + c;
            op[c] = (acc[r][c] != 0.0f || gi == gj) ? 0.0f : -1e30f;
        }
        *reinterpret_cast<float4*>(&g_mbias[gi*Nn + j0 + 4*tx]) = o;
    }
}

// ---------------- projection: xl(->transposed) AND xr in one launch -------
template<int K>
__global__ void __launch_bounds__(256) proj_kernel(
    const float* __restrict__ Xopt,
    const float* __restrict__ Wl, const float* __restrict__ bl,
    const float* __restrict__ Wr, const float* __restrict__ br)
{
    const float* X    = Xopt ? Xopt : g_hln;
    const float* W    = blockIdx.z ? Wr : Wl;
    const float* bias = blockIdx.z ? br : bl;

    __shared__ float A_s[64][33];
    __shared__ float W_s[32][68];
    int m0 = blockIdx.y * 64, n0 = blockIdx.x * 64;
    int t = threadIdx.x, tx = t & 15, ty = t >> 4;

    u64 accp[4][2];
    #pragma unroll
    for (int r = 0; r < 4; r++) { accp[r][0] = 0ull; accp[r][1] = 0ull; }

    for (int kc = 0; kc < K; kc += 32) {
        __syncthreads();
        #pragma unroll
        for (int p = 0; p < 8; p++) {
            int row = (t >> 5) + p*8;
            int col = t & 31;
            A_s[row][col] = X[(m0 + row)*K + kc + col];
        }
        #pragma unroll
        for (int p = 0; p < 8; p++) {
            int kk  = (t >> 6) + p*4;
            int col = t & 63;
            W_s[kk][col] = W[(kc + kk)*Cc + n0 + col];
        }
        __syncthreads();
        #pragma unroll
        for (int kk = 0; kk < 32; kk++) {
            ulonglong2 bv = *reinterpret_cast<const ulonglong2*>(&W_s[kk][4*tx]);
            #pragma unroll
            for (int r = 0; r < 4; r++) {
                u64 ad = dup2(A_s[ty + 16*r][kk]);
                fma2(accp[r][0], ad, bv.x);
                fma2(accp[r][1], ad, bv.y);
            }
        }
    }
    float4 bv4 = *reinterpret_cast<const float4*>(&bias[n0 + 4*tx]);
    if (blockIdx.z == 0) {
        // transposed store: g_xlT[(b*4+h)*32 + d2][node]
        int hq = blockIdx.x;           // n0>>6
        int d2a = 2*tx;                // (n&63)>>1 for n = n0+4tx
        #pragma unroll
        for (int r = 0; r < 4; r++) {
            int m = m0 + ty + 16*r;
            int b = m >> 9, node = m & 511;
            float2 lo = unpack2(accp[r][0]), hi = unpack2(accp[r][1]);
            float2* base = g_xlT + (size_t)((b*4 + hq)*32)*512;
            base[(d2a    )*512 + node] = make_float2(lo.x + bv4.x, lo.y + bv4.y);
            base[(d2a + 1)*512 + node] = make_float2(hi.x + bv4.z, hi.y + bv4.w);
        }
    } else {
        #pragma unroll
        for (int r = 0; r < 4; r++) {
            float2 lo = unpack2(accp[r][0]), hi = unpack2(accp[r][1]);
            float4 o = make_float4(lo.x + bv4.x, lo.y + bv4.y, hi.x + bv4.z, hi.y + bv4.w);
            *reinterpret_cast<float4*>(&g_xr[(m0 + ty + 16*r)*Cc + n0 + 4*tx]) = o;
        }
    }
}

// ---------------- fused GATv2 attention (d-paired, conflict-free) ----------
// grid (16,4,2), 256 threads. Warp w owns rows 4w..4w+3; lane l owns
// j = 2l,2l+1 (score) and d = 2l,2l+1 (output).
__global__ void __launch_bounds__(256) attn_kernel(
    const float* __restrict__ att,
    const float* __restrict__ bias,
    float* __restrict__ outopt)
{
    float* out = outopt ? outopt : g_attout;
    const int b = blockIdx.z, h = blockIdx.y, i0 = blockIdx.x * 32;
    const int t = threadIdx.x, w = t >> 5, l = t & 31;

    __shared__ float2 xlT2[32][66];   // [d2][j], 16B-unit stride 33 (odd) -> conflict-free
    __shared__ float2 xr2 [32][34];   // [row][d2]
    __shared__ float2 p4  [32][66];   // dup pairs (p,p) per j
    __shared__ float2 bt2[32];
    __shared__ float2 ct2[32];

    // load xr as d-pairs
    #pragma unroll
    for (int p = 0; p < 2; p++) {
        int idx = t + p*256;
        int r = idx >> 4, cc = idx & 15;
        float4 v = *reinterpret_cast<const float4*>(&g_xr[(b*Nn + i0 + r)*Cc + h*64 + 4*cc]);
        *reinterpret_cast<float4*>(&xr2[r][2*cc]) = v;
    }
    if (t < 32) {
        float2 a = *reinterpret_cast<const float2*>(&att[h*64 + 2*t]);
        bt2[t] = make_float2(0.4f*a.x, 0.4f*a.y);
        ct2[t] = make_float2(0.6f*a.x, 0.6f*a.y);
    }
    __syncthreads();

    // ar[k] = 0.6 * att . xr[row]  (lane l holds d2=l slice)
    float arr[4];
    #pragma unroll
    for (int k = 0; k < 4; k++) {
        float2 ct = ct2[l];
        float2 xv = xr2[4*w + k][l];
        float pa = ct.x*xv.x + ct.y*xv.y;
        #pragma unroll
        for (int o = 16; o; o >>= 1) pa += __shfl_xor_sync(0xffffffffu, pa, o);
        arr[k] = pa;
    }

    const float2* xsrc = g_xlT + (size_t)((b*4 + h)*32)*512;
    const int d2p = t >> 5, mp = t & 31;   // prefetch coords: d2 = d2p + 8p

    u64 accp[4];
    float psum[4];
    #pragma unroll
    for (int k = 0; k < 4; k++) { accp[k] = 0ull; psum[k] = 0.f; }

    // prefetch chunk 0
    float4 pre[4];
    #pragma unroll
    for (int p = 0; p < 4; p++)
        pre[p] = *reinterpret_cast<const float4*>(xsrc + (d2p + 8*p)*512 + 0 + 2*mp);

    for (int c = 0; c < 8; c++) {
        const int j0 = c * 64;
        __syncthreads();   // all warps done reading xlT2 of previous chunk
        #pragma unroll
        for (int p = 0; p < 4; p++)
            *reinterpret_cast<float4*>(&xlT2[d2p + 8*p][2*mp]) = pre[p];
        __syncthreads();
        if (c < 7) {
            #pragma unroll
            for (int p = 0; p < 4; p++)
                pre[p] = *reinterpret_cast<const float4*>(xsrc + (d2p + 8*p)*512 + (j0 + 64) + 2*mp);
        }

        // ---- score (packed over d) ----
        u64 sp[4][2];
        u64 alp[2] = {0ull, 0ull};
        #pragma unroll
        for (int k = 0; k < 4; k++) { sp[k][0] = 0ull; sp[k][1] = 0ull; }

        #pragma unroll
        for (int d2 = 0; d2 < 32; d2 += 2) {
            ulonglong2 xa = *reinterpret_cast<const ulonglong2*>(&xlT2[d2    ][2*l]); // j0pair,j1pair @d2
            ulonglong2 xb = *reinterpret_cast<const ulonglong2*>(&xlT2[d2 + 1][2*l]); // @d2+1
            ulonglong2 bt = *reinterpret_cast<const ulonglong2*>(&bt2[d2]);
            ulonglong2 ct = *reinterpret_cast<const ulonglong2*>(&ct2[d2]);
            fma2(alp[0], ct.x, xa.x); fma2(alp[1], ct.x, xa.y);
            fma2(alp[0], ct.y, xb.x); fma2(alp[1], ct.y, xb.y);
            #pragma unroll
            for (int k = 0; k < 4; k++) {
                ulonglong2 xr = *reinterpret_cast<const ulonglong2*>(&xr2[4*w + k][d2]);
                u64 z;
                z = add2(xr.x, xa.x) & ABS2MASK; fma2(sp[k][0], bt.x, z);
                z = add2(xr.x, xa.y) & ABS2MASK; fma2(sp[k][1], bt.x, z);
                z = add2(xr.y, xb.x) & ABS2MASK; fma2(sp[k][0], bt.y, z);
                z = add2(xr.y, xb.y) & ABS2MASK; fma2(sp[k][1], bt.y, z);
            }
        }
        float2 a0 = unpack2(alp[0]), a1 = unpack2(alp[1]);
        float al0 = a0.x + a0.y, al1 = a1.x + a1.y;

        // ---- exp + probability write ----
        #pragma unroll
        for (int k = 0; k < 4; k++) {
            float2 mb = *reinterpret_cast<const float2*>(&g_mbias[(i0 + 4*w + k)*Nn + j0 + 2*l]);
            float2 s0v = unpack2(sp[k][0]);
            float2 s1v = unpack2(sp[k][1]);
            float p0 = __expf(s0v.x + s0v.y + arr[k] + al0 + mb.x);
            float p1 = __expf(s1v.x + s1v.y + arr[k] + al1 + mb.y);
            *reinterpret_cast<float4*>(&p4[4*w + k][2*l]) = make_float4(p0, p0, p1, p1);
            psum[k] += p0 + p1;
        }
        __syncwarp();

        // ---- aggregation: lane's d-pair (d2=l), 2 j per step ----
        #pragma unroll 8
        for (int m = 0; m < 32; m++) {
            ulonglong2 xv = *reinterpret_cast<const ulonglong2*>(&xlT2[l][2*m]);
            #pragma unroll
            for (int k = 0; k < 4; k++) {
                ulonglong2 pv = *reinterpret_cast<const ulonglong2*>(&p4[4*w + k][2*m]);
                fma2(accp[k], pv.x, xv.x);
                fma2(accp[k], pv.y, xv.y);
            }
        }
    }

    float2 bv = *reinterpret_cast<const float2*>(&bias[h*64 + 2*l]);
    #pragma unroll
    for (int k = 0; k < 4; k++) {
        float s = psum[k];
        #pragma unroll
        for (int o = 16; o; o >>= 1) s += __shfl_xor_sync(0xffffffffu, s, o);
        float inv = 1.0f / s;
        float2 a = unpack2(accp[k]);
        int i = i0 + 4*w + k;
        float2 o2 = make_float2(a.x*inv + bv.x, a.y*inv + bv.y);
        *reinterpret_cast<float2*>(&out[(b*Nn + i)*Cc + h*64 + 2*l]) = o2;
    }
}

// ---------------- LayerNorm, warp-per-row ----------------------------------
__global__ void __launch_bounds__(256) ln_kernel(
    const float* __restrict__ g,
    const float* __restrict__ be,
    float* __restrict__ outopt,
    int do_relu)
{
    float* out = outopt ? outopt : g_hln;
    int row = blockIdx.x*8 + (threadIdx.x >> 5);
    int l = threadIdx.x & 31;
    const float4* src = reinterpret_cast<const float4*>(&g_attout[row*Cc]);
    float4 a = src[l], c = src[l + 32];
    float s = a.x+a.y+a.z+a.w + c.x+c.y+c.z+c.w;
    #pragma unroll
    for (int o = 16; o; o >>= 1) s += __shfl_xor_sync(0xffffffffu, s, o);
    float mu = s * (1.0f/Cc);
    float4 da = make_float4(a.x-mu, a.y-mu, a.z-mu, a.w-mu);
    float4 dc = make_float4(c.x-mu, c.y-mu, c.z-mu, c.w-mu);
    float v = da.x*da.x+da.y*da.y+da.z*da.z+da.w*da.w
            + dc.x*dc.x+dc.y*dc.y+dc.z*dc.z+dc.w*dc.w;
    #pragma unroll
    for (int o = 16; o; o >>= 1) v += __shfl_xor_sync(0xffffffffu, v, o);
    float rs = rsqrtf(v * (1.0f/Cc) + 1e-5f);
    float4 g4a = reinterpret_cast<const float4*>(g)[l];
    float4 g4c = reinterpret_cast<const float4*>(g)[l + 32];
    float4 b4a = reinterpret_cast<const float4*>(be)[l];
    float4 b4c = reinterpret_cast<const float4*>(be)[l + 32];
    float4 oa = make_float4(da.x*rs*g4a.x + b4a.x, da.y*rs*g4a.y + b4a.y,
                            da.z*rs*g4a.z + b4a.z, da.w*rs*g4a.w + b4a.w);
    float4 oc = make_float4(dc.x*rs*g4c.x + b4c.x, dc.y*rs*g4c.y + b4c.y,
                            dc.z*rs*g4c.z + b4c.z, dc.w*rs*g4c.w + b4c.w);
    if (do_relu) {
        oa = make_float4(fmaxf(oa.x,0.f), fmaxf(oa.y,0.f), fmaxf(oa.z,0.f), fmaxf(oa.w,0.f));
        oc = make_float4(fmaxf(oc.x,0.f), fmaxf(oc.y,0.f), fmaxf(oc.z,0.f), fmaxf(oc.w,0.f));
    }
    float4* dst = reinterpret_cast<float4*>(&out[row*Cc]);
    dst[l] = oa;
    dst[l + 32] = oc;
}

// ---------------- launch ----------------------------------------------------
extern "C" void kernel_launch(void* const* d_in, const int* in_sizes, int n_in,
                              void* d_out, int out_size) {
    const float* x     = (const float*)d_in[0];
    const float* emb   = (const float*)d_in[1];
    const float* w1l   = (const float*)d_in[2];
    const float* b1l   = (const float*)d_in[3];
    const float* w1r   = (const float*)d_in[4];
    const float* b1r   = (const float*)d_in[5];
    const float* att1  = (const float*)d_in[6];
    const float* bias1 = (const float*)d_in[7];
    const float* g1    = (const float*)d_in[8];
    const float* be1   = (const float*)d_in[9];
    const float* w2l   = (const float*)d_in[10];
    const float* b2l   = (const float*)d_in[11];
    const float* w2r   = (const float*)d_in[12];
    const float* b2r   = (const float*)d_in[13];
    const float* att2  = (const float*)d_in[14];
    const float* bias2 = (const float*)d_in[15];
    const float* g2    = (const float*)d_in[16];
    const float* be2   = (const float*)d_in[17];
    float* out = (float*)d_out;

    mask_kernel<<<dim3(8, 16), 256>>>(emb);

    proj_kernel<DIN><<<dim3(4, 16, 2), 256>>>(x, w1l, b1l, w1r, b1r);
    attn_kernel<<<dim3(16, 4, 2), 256>>>(att1, bias1, nullptr);
    ln_kernel<<<128, 256>>>(g1, be1, nullptr, 1);

    proj_kernel<Cc><<<dim3(4, 16, 2), 256>>>(nullptr, w2l, b2l, w2r, b2r);
    attn_kernel<<<dim3(16, 4, 2), 256>>>(att2, bias2, nullptr);
    ln_kernel<<<128, 256>>>(g2, be2, out, 0);
}

// round 5
// speedup vs baseline: 1.3615x; 1.0586x over previous
#include <cuda_runtime.h>
#include <math.h>

#define Bq   2
#define Nn   512
#define DIN  32
#define DHD  64
#define Hh   4
#define Cc   256
#define BN   (Bq*Nn)

typedef unsigned long long u64;

__device__ float  g_mbias[Nn*Nn];
__device__ float2 g_xlT[Bq*Hh*32*512];   // [(b*4+h)*32 + d2][node]
__device__ float  g_xr[BN*Cc];
__device__ float  g_pacc[2*BN*Cc];       // partial weighted sums, [half][row][c]
__device__ float  g_psum[2*BN*Hh];       // partial exp sums, [half][row][h]
__device__ float  g_hln[BN*Cc];

// ---- packed fp32x2 helpers (sm_103a) ----
__device__ __forceinline__ u64 add2(u64 a, u64 b) {
    u64 r; asm("add.rn.f32x2 %0,%1,%2;" : "=l"(r) : "l"(a), "l"(b)); return r;
}
__device__ __forceinline__ void fma2(u64 &d, u64 a, u64 b) {
    asm("fma.rn.f32x2 %0,%1,%2,%3;" : "=l"(d) : "l"(a), "l"(b), "l"(d));
}
__device__ __forceinline__ u64 dup2(float x) {
    u64 r; asm("mov.b64 %0,{%1,%1};" : "=l"(r) : "f"(x)); return r;
}
__device__ __forceinline__ float2 unpack2(u64 v) {
    float2 f; asm("mov.b64 {%0,%1},%2;" : "=f"(f.x), "=f"(f.y) : "l"(v)); return f;
}
#define ABS2MASK 0x7FFFFFFF7FFFFFFFULL

// ---------------- mask bias (ne fused): (ne@ne^T != 0)|eye -> 0/-1e30 ------
__global__ void __launch_bounds__(256) mask_kernel(const float* __restrict__ emb) {
    __shared__ float A_s[32][65];
    __shared__ float B_s[64][65];
    int i0 = blockIdx.y * 32, j0 = blockIdx.x * 64;
    int t = threadIdx.x, tx = t & 15, ty = t >> 4;

    {   // normalize A rows: 8 threads per row
        int r = t >> 3, q = t & 7;
        const float* src = &emb[(i0 + r)*DHD + q*8];
        float4 v0 = *reinterpret_cast<const float4*>(src);
        float4 v1 = *reinterpret_cast<const float4*>(src + 4);
        float s = v0.x*v0.x + v0.y*v0.y + v0.z*v0.z + v0.w*v0.w
                + v1.x*v1.x + v1.y*v1.y + v1.z*v1.z + v1.w*v1.w;
        s += __shfl_xor_sync(0xffffffffu, s, 1);
        s += __shfl_xor_sync(0xffffffffu, s, 2);
        s += __shfl_xor_sync(0xffffffffu, s, 4);
        float inv = rsqrtf(s);
        A_s[r][q*8+0]=v0.x*inv; A_s[r][q*8+1]=v0.y*inv; A_s[r][q*8+2]=v0.z*inv; A_s[r][q*8+3]=v0.w*inv;
        A_s[r][q*8+4]=v1.x*inv; A_s[r][q*8+5]=v1.y*inv; A_s[r][q*8+6]=v1.z*inv; A_s[r][q*8+7]=v1.w*inv;
    }
    {   // normalize B rows: 4 threads per row
        int r = t >> 2, q = t & 3;
        const float* src = &emb[(j0 + r)*DHD + q*16];
        float4 v[4];
        #pragma unroll
        for (int i = 0; i < 4; i++) v[i] = *reinterpret_cast<const float4*>(src + 4*i);
        float s = 0.f;
        #pragma unroll
        for (int i = 0; i < 4; i++) s += v[i].x*v[i].x + v[i].y*v[i].y + v[i].z*v[i].z + v[i].w*v[i].w;
        s += __shfl_xor_sync(0xffffffffu, s, 1);
        s += __shfl_xor_sync(0xffffffffu, s, 2);
        float inv = rsqrtf(s);
        #pragma unroll
        for (int i = 0; i < 4; i++) {
            B_s[r][q*16 + 4*i    ] = v[i].x*inv;
            B_s[r][q*16 + 4*i + 1] = v[i].y*inv;
            B_s[r][q*16 + 4*i + 2] = v[i].z*inv;
            B_s[r][q*16 + 4*i + 3] = v[i].w*inv;
        }
    }
    __syncthreads();

    float acc[2][4];
    #pragma unroll
    for (int r = 0; r < 2; r++)
        #pragma unroll
        for (int c = 0; c < 4; c++) acc[r][c] = 0.f;

    #pragma unroll
    for (int kk = 0; kk < 64; kk++) {
        float a0 = A_s[ty][kk], a1 = A_s[ty + 16][kk];
        float bb[4];
        #pragma unroll
        for (int c = 0; c < 4; c++) bb[c] = B_s[4*tx + c][kk];
        #pragma unroll
        for (int c = 0; c < 4; c++) { acc[0][c] += a0*bb[c]; acc[1][c] += a1*bb[c]; }
    }
    #pragma unroll
    for (int r = 0; r < 2; r++) {
        int gi = i0 + ty + 16*r;
        float4 o;
        float* op = &o.x;
        #pragma unroll
        for (int c = 0; c < 4; c++) {
            int gj = j0 + 4*tx + c;
            op[c] = (acc[r][c] != 0.0f || gi == gj) ? 0.0f : -1e30f;
        }
        *reinterpret_cast<float4*>(&g_mbias[gi*Nn + j0 + 4*tx]) = o;
    }
}

// ---------------- projection: xl(->transposed) AND xr in one launch -------
template<int K>
__global__ void __launch_bounds__(256) proj_kernel(
    const float* __restrict__ Xopt,
    const float* __restrict__ Wl, const float* __restrict__ bl,
    const float* __restrict__ Wr, const float* __restrict__ br)
{
    const float* X    = Xopt ? Xopt : g_hln;
    const float* W    = blockIdx.z ? Wr : Wl;
    const float* bias = blockIdx.z ? br : bl;

    __shared__ float A_s[64][33];
    __shared__ float W_s[32][68];
    int m0 = blockIdx.y * 64, n0 = blockIdx.x * 64;
    int t = threadIdx.x, tx = t & 15, ty = t >> 4;

    u64 accp[4][2];
    #pragma unroll
    for (int r = 0; r < 4; r++) { accp[r][0] = 0ull; accp[r][1] = 0ull; }

    for (int kc = 0; kc < K; kc += 32) {
        __syncthreads();
        #pragma unroll
        for (int p = 0; p < 8; p++) {
            int row = (t >> 5) + p*8;
            int col = t & 31;
            A_s[row][col] = X[(m0 + row)*K + kc + col];
        }
        #pragma unroll
        for (int p = 0; p < 8; p++) {
            int kk  = (t >> 6) + p*4;
            int col = t & 63;
            W_s[kk][col] = W[(kc + kk)*Cc + n0 + col];
        }
        __syncthreads();
        #pragma unroll
        for (int kk = 0; kk < 32; kk++) {
            ulonglong2 bv = *reinterpret_cast<const ulonglong2*>(&W_s[kk][4*tx]);
            #pragma unroll
            for (int r = 0; r < 4; r++) {
                u64 ad = dup2(A_s[ty + 16*r][kk]);
                fma2(accp[r][0], ad, bv.x);
                fma2(accp[r][1], ad, bv.y);
            }
        }
    }
    float4 bv4 = *reinterpret_cast<const float4*>(&bias[n0 + 4*tx]);
    if (blockIdx.z == 0) {
        int hq = blockIdx.x;
        int d2a = 2*tx;
        #pragma unroll
        for (int r = 0; r < 4; r++) {
            int m = m0 + ty + 16*r;
            int b = m >> 9, node = m & 511;
            float2 lo = unpack2(accp[r][0]), hi = unpack2(accp[r][1]);
            float2* base = g_xlT + (size_t)((b*4 + hq)*32)*512;
            base[(d2a    )*512 + node] = make_float2(lo.x + bv4.x, lo.y + bv4.y);
            base[(d2a + 1)*512 + node] = make_float2(hi.x + bv4.z, hi.y + bv4.w);
        }
    } else {
        #pragma unroll
        for (int r = 0; r < 4; r++) {
            float2 lo = unpack2(accp[r][0]), hi = unpack2(accp[r][1]);
            float4 o = make_float4(lo.x + bv4.x, lo.y + bv4.y, hi.x + bv4.z, hi.y + bv4.w);
            *reinterpret_cast<float4*>(&g_xr[(m0 + ty + 16*r)*Cc + n0 + 4*tx]) = o;
        }
    }
}

// ---------------- fused GATv2 attention, j-split into 2 halves -------------
// grid (16, 4, 4): z = b*2 + half. 32 rows/block, 4 j-chunks per block.
// Writes partial acc (no normalization) + partial exp-sum; ln combines.
__global__ void __launch_bounds__(256) attn_kernel(const float* __restrict__ att)
{
    const int z = blockIdx.z, b = z >> 1, half = z & 1;
    const int h = blockIdx.y, i0 = blockIdx.x * 32;
    const int t = threadIdx.x, w = t >> 5, l = t & 31;

    __shared__ float2 xlT2[32][66];   // [d2][j] local, stride 33 (odd) 16B units
    __shared__ float2 xr2 [32][34];   // [row][d2]
    __shared__ float2 p4  [32][66];   // dup pairs (p,p)
    __shared__ float2 bt2[32];
    __shared__ float2 ct2[32];

    #pragma unroll
    for (int p = 0; p < 2; p++) {
        int idx = t + p*256;
        int r = idx >> 4, cc = idx & 15;
        float4 v = *reinterpret_cast<const float4*>(&g_xr[(b*Nn + i0 + r)*Cc + h*64 + 4*cc]);
        *reinterpret_cast<float4*>(&xr2[r][2*cc]) = v;
    }
    if (t < 32) {
        float2 a = *reinterpret_cast<const float2*>(&att[h*64 + 2*t]);
        bt2[t] = make_float2(0.4f*a.x, 0.4f*a.y);
        ct2[t] = make_float2(0.6f*a.x, 0.6f*a.y);
    }
    __syncthreads();

    float arr[4];
    #pragma unroll
    for (int k = 0; k < 4; k++) {
        float2 ct = ct2[l];
        float2 xv = xr2[4*w + k][l];
        float pa = ct.x*xv.x + ct.y*xv.y;
        #pragma unroll
        for (int o = 16; o; o >>= 1) pa += __shfl_xor_sync(0xffffffffu, pa, o);
        arr[k] = pa;
    }

    const float2* xsrc = g_xlT + (size_t)((b*4 + h)*32)*512;
    const int jbase = half * 256;
    const int d2p = t >> 5, mp = t & 31;

    u64 accp[4];
    float psum[4];
    #pragma unroll
    for (int k = 0; k < 4; k++) { accp[k] = 0ull; psum[k] = 0.f; }

    float4 pre[4];
    #pragma unroll
    for (int p = 0; p < 4; p++)
        pre[p] = *reinterpret_cast<const float4*>(xsrc + (d2p + 8*p)*512 + jbase + 2*mp);

    for (int c = 0; c < 4; c++) {
        const int j0 = jbase + c * 64;
        __syncthreads();
        #pragma unroll
        for (int p = 0; p < 4; p++)
            *reinterpret_cast<float4*>(&xlT2[d2p + 8*p][2*mp]) = pre[p];
        __syncthreads();
        if (c < 3) {
            #pragma unroll
            for (int p = 0; p < 4; p++)
                pre[p] = *reinterpret_cast<const float4*>(xsrc + (d2p + 8*p)*512 + (j0 + 64) + 2*mp);
        }

        // ---- score (packed over d) ----
        u64 sp[4][2];
        u64 alp[2] = {0ull, 0ull};
        #pragma unroll
        for (int k = 0; k < 4; k++) { sp[k][0] = 0ull; sp[k][1] = 0ull; }

        #pragma unroll
        for (int d2 = 0; d2 < 32; d2 += 2) {
            ulonglong2 xa = *reinterpret_cast<const ulonglong2*>(&xlT2[d2    ][2*l]);
            ulonglong2 xb = *reinterpret_cast<const ulonglong2*>(&xlT2[d2 + 1][2*l]);
            ulonglong2 bt = *reinterpret_cast<const ulonglong2*>(&bt2[d2]);
            ulonglong2 ct = *reinterpret_cast<const ulonglong2*>(&ct2[d2]);
            fma2(alp[0], ct.x, xa.x); fma2(alp[1], ct.x, xa.y);
            fma2(alp[0], ct.y, xb.x); fma2(alp[1], ct.y, xb.y);
            #pragma unroll
            for (int k = 0; k < 4; k++) {
                ulonglong2 xr = *reinterpret_cast<const ulonglong2*>(&xr2[4*w + k][d2]);
                u64 z;
                z = add2(xr.x, xa.x) & ABS2MASK; fma2(sp[k][0], bt.x, z);
                z = add2(xr.x, xa.y) & ABS2MASK; fma2(sp[k][1], bt.x, z);
                z = add2(xr.y, xb.x) & ABS2MASK; fma2(sp[k][0], bt.y, z);
                z = add2(xr.y, xb.y) & ABS2MASK; fma2(sp[k][1], bt.y, z);
            }
        }
        float2 a0 = unpack2(alp[0]), a1 = unpack2(alp[1]);
        float al0 = a0.x + a0.y, al1 = a1.x + a1.y;

        // ---- exp + probability write ----
        #pragma unroll
        for (int k = 0; k < 4; k++) {
            float2 mb = *reinterpret_cast<const float2*>(&g_mbias[(i0 + 4*w + k)*Nn + j0 + 2*l]);
            float2 s0v = unpack2(sp[k][0]);
            float2 s1v = unpack2(sp[k][1]);
            float p0 = __expf(s0v.x + s0v.y + arr[k] + al0 + mb.x);
            float p1 = __expf(s1v.x + s1v.y + arr[k] + al1 + mb.y);
            *reinterpret_cast<float4*>(&p4[4*w + k][2*l]) = make_float4(p0, p0, p1, p1);
            psum[k] += p0 + p1;
        }
        __syncwarp();

        // ---- aggregation ----
        #pragma unroll 8
        for (int m = 0; m < 32; m++) {
            ulonglong2 xv = *reinterpret_cast<const ulonglong2*>(&xlT2[l][2*m]);
            #pragma unroll
            for (int k = 0; k < 4; k++) {
                ulonglong2 pv = *reinterpret_cast<const ulonglong2*>(&p4[4*w + k][2*m]);
                fma2(accp[k], pv.x, xv.x);
                fma2(accp[k], pv.y, xv.y);
            }
        }
    }

    // ---- write partials ----
    #pragma unroll
    for (int k = 0; k < 4; k++) {
        float s = psum[k];
        #pragma unroll
        for (int o = 16; o; o >>= 1) s += __shfl_xor_sync(0xffffffffu, s, o);
        int row = b*Nn + i0 + 4*w + k;
        float2 a = unpack2(accp[k]);
        *reinterpret_cast<float2*>(&g_pacc[(half*BN + row)*Cc + h*64 + 2*l]) = a;
        if (l == 0) g_psum[(half*BN + row)*Hh + h] = s;
    }
}

// ---------------- combine + bias + LayerNorm (+ReLU), warp-per-row ---------
__global__ void __launch_bounds__(256) ln_kernel(
    const float* __restrict__ g,
    const float* __restrict__ be,
    const float* __restrict__ abias,
    float* __restrict__ outopt,
    int do_relu)
{
    float* out = outopt ? outopt : g_hln;
    int row = blockIdx.x*8 + (threadIdx.x >> 5);
    int l = threadIdx.x & 31;

    // channel groups: c0 = 4l (h = l>>4), c1 = 128+4l (h = 2 + (l>>4))
    int h0 = l >> 4, h1 = 2 + (l >> 4);
    float inv0 = 1.0f / (g_psum[row*Hh + h0] + g_psum[(BN + row)*Hh + h0]);
    float inv1 = 1.0f / (g_psum[row*Hh + h1] + g_psum[(BN + row)*Hh + h1]);

    const float4* p0 = reinterpret_cast<const float4*>(&g_pacc[row*Cc]);
    const float4* p1 = reinterpret_cast<const float4*>(&g_pacc[(BN + row)*Cc]);
    float4 xa0 = p0[l],      xa1 = p1[l];
    float4 xc0 = p0[l + 32], xc1 = p1[l + 32];
    float4 ab_a = reinterpret_cast<const float4*>(abias)[l];
    float4 ab_c = reinterpret_cast<const float4*>(abias)[l + 32];

    float4 a = make_float4((xa0.x + xa1.x)*inv0 + ab_a.x, (xa0.y + xa1.y)*inv0 + ab_a.y,
                           (xa0.z + xa1.z)*inv0 + ab_a.z, (xa0.w + xa1.w)*inv0 + ab_a.w);
    float4 c = make_float4((xc0.x + xc1.x)*inv1 + ab_c.x, (xc0.y + xc1.y)*inv1 + ab_c.y,
                           (xc0.z + xc1.z)*inv1 + ab_c.z, (xc0.w + xc1.w)*inv1 + ab_c.w);

    float s = a.x+a.y+a.z+a.w + c.x+c.y+c.z+c.w;
    #pragma unroll
    for (int o = 16; o; o >>= 1) s += __shfl_xor_sync(0xffffffffu, s, o);
    float mu = s * (1.0f/Cc);
    float4 da = make_float4(a.x-mu, a.y-mu, a.z-mu, a.w-mu);
    float4 dc = make_float4(c.x-mu, c.y-mu, c.z-mu, c.w-mu);
    float v = da.x*da.x+da.y*da.y+da.z*da.z+da.w*da.w
            + dc.x*dc.x+dc.y*dc.y+dc.z*dc.z+dc.w*dc.w;
    #pragma unroll
    for (int o = 16; o; o >>= 1) v += __shfl_xor_sync(0xffffffffu, v, o);
    float rs = rsqrtf(v * (1.0f/Cc) + 1e-5f);
    float4 g4a = reinterpret_cast<const float4*>(g)[l];
    float4 g4c = reinterpret_cast<const float4*>(g)[l + 32];
    float4 b4a = reinterpret_cast<const float4*>(be)[l];
    float4 b4c = reinterpret_cast<const float4*>(be)[l + 32];
    float4 oa = make_float4(da.x*rs*g4a.x + b4a.x, da.y*rs*g4a.y + b4a.y,
                            da.z*rs*g4a.z + b4a.z, da.w*rs*g4a.w + b4a.w);
    float4 oc = make_float4(dc.x*rs*g4c.x + b4c.x, dc.y*rs*g4c.y + b4c.y,
                            dc.z*rs*g4c.z + b4c.z, dc.w*rs*g4c.w + b4c.w);
    if (do_relu) {
        oa = make_float4(fmaxf(oa.x,0.f), fmaxf(oa.y,0.f), fmaxf(oa.z,0.f), fmaxf(oa.w,0.f));
        oc = make_float4(fmaxf(oc.x,0.f), fmaxf(oc.y,0.f), fmaxf(oc.z,0.f), fmaxf(oc.w,0.f));
    }
    float4* dst = reinterpret_cast<float4*>(&out[row*Cc]);
    dst[l] = oa;
    dst[l + 32] = oc;
}

// ---------------- launch ----------------------------------------------------
extern "C" void kernel_launch(void* const* d_in, const int* in_sizes, int n_in,
                              void* d_out, int out_size) {
    const float* x     = (const float*)d_in[0];
    const float* emb   = (const float*)d_in[1];
    const float* w1l   = (const float*)d_in[2];
    const float* b1l   = (const float*)d_in[3];
    const float* w1r   = (const float*)d_in[4];
    const float* b1r   = (const float*)d_in[5];
    const float* att1  = (const float*)d_in[6];
    const float* bias1 = (const float*)d_in[7];
    const float* g1    = (const float*)d_in[8];
    const float* be1   = (const float*)d_in[9];
    const float* w2l   = (const float*)d_in[10];
    const float* b2l   = (const float*)d_in[11];
    const float* w2r   = (const float*)d_in[12];
    const float* b2r   = (const float*)d_in[13];
    const float* att2  = (const float*)d_in[14];
    const float* bias2 = (const float*)d_in[15];
    const float* g2    = (const float*)d_in[16];
    const float* be2   = (const float*)d_in[17];
    float* out = (float*)d_out;

    mask_kernel<<<dim3(8, 16), 256>>>(emb);

    proj_kernel<DIN><<<dim3(4, 16, 2), 256>>>(x, w1l, b1l, w1r, b1r);
    attn_kernel<<<dim3(16, 4, 4), 256>>>(att1);
    ln_kernel<<<128, 256>>>(g1, be1, bias1, nullptr, 1);

    proj_kernel<Cc><<<dim3(4, 16, 2), 256>>>(nullptr, w2l, b2l, w2r, b2r);
    attn_kernel<<<dim3(16, 4, 4), 256>>>(att2);
    ln_kernel<<<128, 256>>>(g2, be2, bias2, out, 0);
}